// round 13
// baseline (speedup 1.0000x reference)
#include <cuda_runtime.h>
#include <cstdint>

#define NTAGS 48
#define SEQ 512
#define BSZ 64
#define NTRANS (NTAGS*NTAGS)          // 2304
#define RST 50                         // smem row stride (floats)
#define TILE_PAD (NTAGS*RST)           // 2400 floats = 9600 B
#define STAGES 5
#define NTHREADS 384
#define LOG2E_F 1.4426950408889634f
#define LN2_D   0.6931471805599453
#define START_TAG 46
#define END_TAG 47

__device__ float g_part[BSZ];
__device__ unsigned int g_done = 0;

__device__ __forceinline__ float ex2f(float x){
    float y; asm("ex2.approx.ftz.f32 %0, %1;" : "=f"(y) : "f"(x)); return y;
}
__device__ __forceinline__ float lg2f(float x){
    float y; asm("lg2.approx.ftz.f32 %0, %1;" : "=f"(y) : "f"(x)); return y;
}
__device__ __forceinline__ void cp8(uint32_t s, const void* g){
    asm volatile("cp.async.ca.shared.global [%0], [%1], 8;" :: "r"(s), "l"(g));
}
__device__ __forceinline__ void cp_commit(){ asm volatile("cp.async.commit_group;"); }
__device__ __forceinline__ void cp_wait2(){ asm volatile("cp.async.wait_group 2;"); }
__device__ __forceinline__ void cp_wait3(){ asm volatile("cp.async.wait_group 3;"); }

__global__ __launch_bounds__(NTHREADS, 1)
void crf_fwd_kernel(const float* __restrict__ tr,
                    const int* __restrict__ tgt,
                    float* __restrict__ out)
{
    __shared__ __align__(16) float buf[STAGES][TILE_PAD];  // 48000 B
    __shared__ __align__(16) float vbuf[2][NTAGS];
    __shared__ float scalebuf[2];
    __shared__ float tsc_sh;
    __shared__ unsigned int rank_sh;
    __shared__ unsigned char tg[SEQ];

    const int tid = threadIdx.x;
    const int b   = blockIdx.x;
    const float* trb = tr + (size_t)b * SEQ * NTRANS;

    // ---- targets ----
    if (tid < SEQ){
        int v = tgt[(size_t)b * SEQ + tid];
        tg[tid] = (unsigned char)(((unsigned)v < NTAGS) ? v : 0);
    }
    if (tid == 0) tsc_sh = 0.f;
    __syncthreads();

    // ---- target_score: all 512 gathers in the prologue, off the recurrence ----
    {
        float acc = 0.f;
        if (tid < SEQ){
            int pr = (tid == 0) ? START_TAG : (int)tg[tid-1];
            int cu = (int)tg[tid];
            acc = __ldg(trb + (size_t)tid * NTRANS + pr * NTAGS + cu);
        }
        #pragma unroll
        for (int m = 16; m > 0; m >>= 1) acc += __shfl_xor_sync(0xffffffffu, acc, m);
        if ((tid & 31) == 0) atomicAdd(&tsc_sh, acc);
    }

    const int w   = tid >> 5;
    const int l   = tid & 31;
    const int col = (w << 2) + (l & 3);   // column 0..47
    const int q   = l >> 2;               // rows 6q..6q+5
    const int r0  = q * 6;

    // 8B cp.async chunk coords (3 chunks/thread, 1152 per tile)
    const int cA = tid, cB = tid + NTHREADS, cC = tid + 2*NTHREADS;
    const uint32_t smA = (uint32_t)((cA/24)*(RST*4) + (cA%24)*8);
    const uint32_t smB = (uint32_t)((cB/24)*(RST*4) + (cB%24)*8);
    const uint32_t smC = (uint32_t)((cC/24)*(RST*4) + (cC%24)*8);
    const int gmA = (cA/24)*NTAGS + (cA%24)*2;
    const int gmB = (cB/24)*NTAGS + (cB%24)*2;
    const int gmC = (cC/24)*NTAGS + (cC%24)*2;
    const uint32_t sbase = (uint32_t)__cvta_generic_to_shared(&buf[0][0]);

    auto prefetch = [&](int tile_idx, int stg){
        uint32_t sb = sbase + (uint32_t)stg * (TILE_PAD*4);
        const float* gb = trb + (size_t)tile_idx * NTRANS;
        cp8(sb + smA, gb + gmA);
        cp8(sb + smB, gb + gmB);
        cp8(sb + smC, gb + gmC);
    };

    prefetch(0,0); cp_commit();
    prefetch(1,1); cp_commit();
    prefetch(2,2); cp_commit();
    prefetch(3,3); cp_commit();
    prefetch(4,4); cp_commit();

    cp_wait3();            // tiles 0,1 complete
    __syncthreads();

    // ---- init (t = 0) ----
    const float* b0 = &buf[0][0];
    const int P0 = __float2int_rn(b0[START_TAG*RST] * LOG2E_F);
    float v0 = ex2f(fmaf(b0[START_TAG*RST + col], LOG2E_F, (float)(-P0)));
    if (q == 0) vbuf[0][col] = v0;

    int Ksum = 0, kcur = 0;   // tid 4 only
    if (tid == 4){
        int e = (__float_as_int(v0) >> 23) & 255;   // v0 here is col 0
        kcur = e - 127;
        scalebuf[1] = __int_as_float((127 - kcur) << 23);
    }

    // Etr for step 1 from tile 1
    float E0,E1,E2,E3,E4,E5;
    {
        const float* tn = &buf[1][0];
        E0 = ex2f(tn[(r0  )*RST + col] * LOG2E_F);
        E1 = ex2f(tn[(r0+1)*RST + col] * LOG2E_F);
        E2 = ex2f(tn[(r0+2)*RST + col] * LOG2E_F);
        E3 = ex2f(tn[(r0+3)*RST + col] * LOG2E_F);
        E4 = ex2f(tn[(r0+4)*RST + col] * LOG2E_F);
        E5 = ex2f(tn[(r0+5)*RST + col] * LOG2E_F);
    }

    int st = 1;                                  // stage holding tile t
    for (int t = 1; t < SEQ; ++t){
        cp_wait2();        // tiles <= t+1 complete
        __syncthreads();   // vbuf/scalebuf of t-1 visible; stage (t-1)%5 free

        const int stp = (st == 0) ? 4 : st - 1;
        const int stn = (st == 4) ? 0 : st + 1;
        if (t + 4 < SEQ) prefetch(t + 4, stp);
        cp_commit();       // uniform group count

        const float  sc = scalebuf[t & 1];
        const float* vp = &vbuf[(t-1) & 1][0];
        const float2* vp2 = (const float2*)vp;
        float2 va = vp2[3*q], vb = vp2[3*q+1], vc = vp2[3*q+2];

        // off-path: Etr for step t+1 from tile t+1 (stale data at t=SEQ-1, unused)
        float F0,F1,F2,F3,F4,F5;
        {
            const float* tn = &buf[stn][0];
            F0 = ex2f(tn[(r0  )*RST + col] * LOG2E_F);
            F1 = ex2f(tn[(r0+1)*RST + col] * LOG2E_F);
            F2 = ex2f(tn[(r0+2)*RST + col] * LOG2E_F);
            F3 = ex2f(tn[(r0+3)*RST + col] * LOG2E_F);
            F4 = ex2f(tn[(r0+4)*RST + col] * LOG2E_F);
            F5 = ex2f(tn[(r0+5)*RST + col] * LOG2E_F);
        }

        // critical chain (E regs from previous iter)
        float s01 = fmaf(E1, va.y, E0 * va.x);
        float s23 = fmaf(E3, vb.y, E2 * vb.x);
        float s45 = fmaf(E5, vc.y, E4 * vc.x);
        float s = (s01 + s23) + s45;
        s += __shfl_xor_sync(0xffffffffu, s, 4);
        s += __shfl_xor_sync(0xffffffffu, s, 8);
        s += __shfl_xor_sync(0xffffffffu, s, 16);
        float v = s * sc;
        if (q == 0) vbuf[t & 1][col] = v;

        if (tid == 4){
            Ksum += kcur;
            float w0 = vp[0];                     // 2-step-stale scale source
            int e = (__float_as_int(w0) >> 23) & 255;
            kcur = e - 127;
            scalebuf[(t+1) & 1] = __int_as_float((127 - e + 127) << 23);
        }

        E0=F0; E1=F1; E2=F2; E3=F3; E4=F4; E5=F5;
        st = stn;
    }

    __syncthreads();
    // ---- per-block result + threadfence reduction (single-kernel finalize) ----
    if (tid == 4){
        float vf = vbuf[(SEQ-1) & 1][END_TAG];
        int   eu = ((__float_as_int(vf) >> 23) & 255) - 127;
        float mu = __int_as_float((__float_as_int(vf) & 0x807FFFFF) | 0x3F800000);
        double log2u = (double)(eu + P0 + Ksum) + (double)lg2f(mu);
        g_part[b] = (float)(LN2_D * log2u - (double)tsc_sh);
        __threadfence();
        rank_sh = atomicAdd(&g_done, 1u);
    }
    __syncthreads();

    if (rank_sh == BSZ - 1){                      // last block finalizes
        if (tid < 32){
            double vs = (double)__ldcg(&g_part[tid]) + (double)__ldcg(&g_part[tid + 32]);
            #pragma unroll
            for (int m = 16; m > 0; m >>= 1)
                vs += __shfl_xor_sync(0xffffffffu, vs, m);
            if (tid == 0){
                out[0] = (float)(vs * (1.0 / (double)BSZ));
                atomicExch(&g_done, 0u);          // reset for next graph replay
            }
        }
    }
}

extern "C" void kernel_launch(void* const* d_in, const int* in_sizes, int n_in,
                              void* d_out, int out_size)
{
    const float* tr  = (const float*)d_in[0];
    const int*   tgt = (const int*)d_in[1];
    float*       out = (float*)d_out;

    crf_fwd_kernel<<<BSZ, NTHREADS>>>(tr, tgt, out);
}

// round 15
// speedup vs baseline: 1.3432x; 1.3432x over previous
#include <cuda_runtime.h>
#include <cstdint>

#define NTAGS 48
#define SEQ 512
#define BSZ 64
#define NTRANS (NTAGS*NTAGS)      // 2304
#define CCH 7                     // chunks per batch
#define LCH 73                    // steps per chunk: 7*73 = 511 (t = 1..511)
#define RST 50                    // fp32 tile row stride (floats), conflict-free
#define STAGES 3
#define NTH 128
#define LOG2E_F 1.4426950408889634f
#define LN2_D   0.6931471805599453
#define START_TAG 46
#define END_TAG 47

__device__ float g_P[BSZ][CCH][NTAGS][NTAGS];   // 4.1 MB chunk matrices (fp32)
__device__ int   g_K[BSZ][CCH];                 // per-chunk power-of-2 exponent
__device__ float g_part[BSZ];
__device__ unsigned int g_done = 0;

__device__ __forceinline__ float ex2f(float x){
    float y; asm("ex2.approx.ftz.f32 %0, %1;" : "=f"(y) : "f"(x)); return y;
}
__device__ __forceinline__ float lg2f(float x){
    float y; asm("lg2.approx.ftz.f32 %0, %1;" : "=f"(y) : "f"(x)); return y;
}
// pack two f32 into bf16x2: lo half = 'lo', hi half = 'hi'
__device__ __forceinline__ uint32_t packbf(float hi, float lo){
    uint32_t r; asm("cvt.rn.bf16x2.f32 %0, %1, %2;" : "=r"(r) : "f"(hi), "f"(lo)); return r;
}
__device__ __forceinline__ void cp8(uint32_t s, const void* g){
    asm volatile("cp.async.ca.shared.global [%0], [%1], 8;" :: "r"(s), "l"(g));
}
__device__ __forceinline__ void mma16816(float d[4],
    uint32_t a0, uint32_t a1, uint32_t a2, uint32_t a3,
    uint32_t b0, uint32_t b1,
    float c0, float c1, float c2, float c3)
{
    asm volatile("mma.sync.aligned.m16n8k16.row.col.f32.bf16.bf16.f32 "
                 "{%0,%1,%2,%3}, {%4,%5,%6,%7}, {%8,%9}, {%10,%11,%12,%13};"
                 : "=f"(d[0]), "=f"(d[1]), "=f"(d[2]), "=f"(d[3])
                 : "r"(a0), "r"(a1), "r"(a2), "r"(a3), "r"(b0), "r"(b1),
                   "f"(c0), "f"(c1), "f"(c2), "f"(c3));
}

// ---------------------------------------------------------------------------
// Kernel 1: each CTA computes P_c = prod_{t in chunk} exp(tr_t)  (48x48)
// grid = (CCH, BSZ), 128 threads. Warps 0-2: 16-row slices via mma chain
// (D fragments convert in-registers to next step's A fragments). All 4 warps
// produce E = exp(tile) in bf16 (transposed, k-contiguous) one step ahead.
// ---------------------------------------------------------------------------
__global__ __launch_bounds__(NTH)
void crf_chunk_kernel(const float* __restrict__ tr)
{
    __shared__ __align__(16) float    tile[STAGES][NTAGS*RST]; // 28800 B
    __shared__ __align__(16) uint32_t ET[2][NTAGS*25];         // 9600 B: [n][k] bf16 pairs
    __shared__ int k_sh[3];

    const int c = blockIdx.x, b = blockIdx.y;
    const float* trb = tr + (size_t)b * SEQ * NTRANS;
    const int tbeg = 1 + LCH * c;
    const int tend = tbeg + LCH - 1;

    const int tid  = threadIdx.x;
    const int w    = tid >> 5, lane = tid & 31;
    const int g    = lane >> 2, tq = lane & 3;

    // cp.async: 9 x 8B chunks per thread (1152 per tile)
    uint32_t smo[9]; int gmo[9];
    #pragma unroll
    for (int k = 0; k < 9; ++k){
        int ch = tid + NTH * k;
        int row = ch / 24, off = ch % 24;
        smo[k] = (uint32_t)(row * (RST*4) + off * 8);
        gmo[k] = row * NTAGS + off * 2;
    }
    const uint32_t sb0 = (uint32_t)__cvta_generic_to_shared(&tile[0][0]);

    // exp duty: 9 bf16-pairs per thread (2304 elems / 128 thr)
    int eread[9], ewrite[9];
    #pragma unroll
    for (int m = 0; m < 9; ++m){
        int p = tid + NTH * m;
        int j = p % NTAGS, ih = p / NTAGS;   // ih 0..23 (k-pair), j = dest col
        eread[m]  = (2*ih) * RST + j;        // tile[i][j], i = 2*ih
        ewrite[m] = j * 25 + ih;             // ET word: [n=j][kpair=ih]
    }

    auto prefetch = [&](int t){
        uint32_t sb = sb0 + (uint32_t)(t % STAGES) * (NTAGS*RST*4);
        const float* gb = trb + (size_t)t * NTRANS;
        #pragma unroll
        for (int k = 0; k < 9; ++k) cp8(sb + smo[k], gb + gmo[k]);
    };

    prefetch(tbeg);     asm volatile("cp.async.commit_group;");
    prefetch(tbeg + 1); asm volatile("cp.async.commit_group;");
    prefetch(tbeg + 2); asm volatile("cp.async.commit_group;");
    asm volatile("cp.async.wait_group 2;");   // tile tbeg resident
    __syncthreads();

    // E(tbeg) -> ET[0]
    {
        const float* tl = &tile[tbeg % STAGES][0];
        #pragma unroll
        for (int m = 0; m < 9; ++m){
            float lo = ex2f(tl[eread[m]      ] * LOG2E_F);
            float hi = ex2f(tl[eread[m] + RST] * LOG2E_F);
            ET[0][ewrite[m]] = packbf(hi, lo);
        }
    }
    __syncthreads();

    // P slice = identity rows [16w, 16w+16)
    float P[6][4];
    const int R0 = 16 * w + g;
    #pragma unroll
    for (int nt = 0; nt < 6; ++nt){
        int C0 = nt * 8 + tq * 2;
        P[nt][0] = (R0     == C0    ) ? 1.f : 0.f;
        P[nt][1] = (R0     == C0 + 1) ? 1.f : 0.f;
        P[nt][2] = (R0 + 8 == C0    ) ? 1.f : 0.f;
        P[nt][3] = (R0 + 8 == C0 + 1) ? 1.f : 0.f;
    }
    int Kw = 0;

    int lp = 0;
    for (int t = tbeg; t <= tend; ++t, lp ^= 1){
        if (t + 3 <= tend) prefetch(t + 3);          // stage (t+3)%3 == t%3 (free)
        asm volatile("cp.async.commit_group;");      // uniform group count
        asm volatile("cp.async.wait_group 2;");      // tiles <= t+1 resident

        if (w < 3){
            // exact pow2 rescale from the diagonal entry P[16w][16w] (lane 0, nt=2w)
            float diag = __shfl_sync(0xffffffffu, P[2*w][0], 0);
            int   eb   = (__float_as_int(diag) >> 23) & 255;
            float s    = __int_as_float((254 - eb) << 23);   // 2^-(eb-127)
            Kw += eb - 127;
            #pragma unroll
            for (int nt = 0; nt < 6; ++nt){
                P[nt][0] *= s; P[nt][1] *= s; P[nt][2] *= s; P[nt][3] *= s;
            }
            // D fragments -> A fragments (in registers)
            uint32_t A[3][4];
            #pragma unroll
            for (int kt = 0; kt < 3; ++kt){
                A[kt][0] = packbf(P[2*kt  ][1], P[2*kt  ][0]);
                A[kt][1] = packbf(P[2*kt  ][3], P[2*kt  ][2]);
                A[kt][2] = packbf(P[2*kt+1][1], P[2*kt+1][0]);
                A[kt][3] = packbf(P[2*kt+1][3], P[2*kt+1][2]);
            }
            // P <- P * E
            const uint32_t* Eb = &ET[lp][0];
            #pragma unroll
            for (int nt = 0; nt < 6; ++nt){
                int base = (nt*8 + g) * 25 + tq;
                float d[4] = {0.f, 0.f, 0.f, 0.f};
                #pragma unroll
                for (int kt = 0; kt < 3; ++kt){
                    uint32_t b0 = Eb[base + kt*8];
                    uint32_t b1 = Eb[base + kt*8 + 4];
                    mma16816(d, A[kt][0], A[kt][1], A[kt][2], A[kt][3],
                             b0, b1, d[0], d[1], d[2], d[3]);
                }
                P[nt][0] = d[0]; P[nt][1] = d[1]; P[nt][2] = d[2]; P[nt][3] = d[3];
            }
        }
        // E(t+1) -> ET[lp^1] (all 4 warps)
        if (t < tend){
            const float* tl = &tile[(t+1) % STAGES][0];
            uint32_t* Ew = &ET[lp ^ 1][0];
            #pragma unroll
            for (int m = 0; m < 9; ++m){
                float lo = ex2f(tl[eread[m]      ] * LOG2E_F);
                float hi = ex2f(tl[eread[m] + RST] * LOG2E_F);
                Ew[ewrite[m]] = packbf(hi, lo);
            }
        }
        __syncthreads();
    }

    // align warp scales (exact pow2) and store P_c
    if (w < 3 && lane == 0) k_sh[w] = Kw;
    __syncthreads();
    if (w < 3){
        int kmax = max(k_sh[0], max(k_sh[1], k_sh[2]));
        int d = Kw - kmax;                               // <= 0
        float s = (d <= -126) ? 0.f : __int_as_float((127 + d) << 23);
        float* gp = &g_P[b][c][0][0];
        #pragma unroll
        for (int nt = 0; nt < 6; ++nt){
            int C0 = nt * 8 + tq * 2;
            gp[(R0    )*NTAGS + C0    ] = P[nt][0] * s;
            gp[(R0    )*NTAGS + C0 + 1] = P[nt][1] * s;
            gp[(R0 + 8)*NTAGS + C0    ] = P[nt][2] * s;
            gp[(R0 + 8)*NTAGS + C0 + 1] = P[nt][3] * s;
        }
        if (tid == 0) g_K[b][c] = kmax;
    }
}

// ---------------------------------------------------------------------------
// Kernel 2: per batch, u0 through the 7 chunk matrices + target_score + mean
// ---------------------------------------------------------------------------
__global__ __launch_bounds__(NTH)
void crf_combine_kernel(const float* __restrict__ tr,
                        const int*   __restrict__ tgt,
                        float* __restrict__ out)
{
    __shared__ float u_sh[NTAGS];
    __shared__ float red[4];
    __shared__ float tsc_sh;
    __shared__ int   ks_sh;
    __shared__ unsigned int rank_sh;
    __shared__ unsigned char tgs[SEQ];

    const int b = blockIdx.x, tid = threadIdx.x;
    const float* trb = tr + (size_t)b * SEQ * NTRANS;

    #pragma unroll
    for (int k = 0; k < 4; ++k){
        int i = tid + NTH * k;
        int v = tgt[(size_t)b * SEQ + i];
        tgs[i] = (unsigned char)(((unsigned)v < NTAGS) ? v : 0);
    }
    __syncthreads();

    // target_score (deterministic tree)
    float acc = 0.f;
    #pragma unroll
    for (int k = 0; k < 4; ++k){
        int t = tid + NTH * k;
        int pr = (t == 0) ? START_TAG : (int)tgs[t-1];
        acc += __ldg(trb + (size_t)t * NTRANS + pr * NTAGS + (int)tgs[t]);
    }
    #pragma unroll
    for (int m = 16; m > 0; m >>= 1) acc += __shfl_xor_sync(0xffffffffu, acc, m);
    if ((tid & 31) == 0) red[tid >> 5] = acc;
    __syncthreads();
    if (tid == 0) tsc_sh = (red[0] + red[1]) + (red[2] + red[3]);

    // u0 = exp(tr_0[START,:])
    if (tid < NTAGS) u_sh[tid] = ex2f(__ldg(trb + START_TAG * NTAGS + tid) * LOG2E_F);
    __syncthreads();

    int Ktot = 0;
    for (int c = 0; c < CCH; ++c){
        float s = 0.f;
        if (tid < NTAGS){
            const float* Pc = &g_P[b][c][0][0];
            #pragma unroll 8
            for (int i = 0; i < NTAGS; ++i)
                s = fmaf(u_sh[i], Pc[i * NTAGS + tid], s);
        }
        __syncthreads();                 // all reads of u_sh done
        if (tid == 0){
            int e = (__float_as_int(s) >> 23) & 255;
            ks_sh = e - 127;
        }
        __syncthreads();
        int kk = ks_sh;
        if (tid < NTAGS) u_sh[tid] = s * __int_as_float((127 - kk) << 23);
        Ktot += kk + g_K[b][c];
        __syncthreads();
    }

    if (tid == 0){
        float uf = u_sh[END_TAG];
        int   eu = ((__float_as_int(uf) >> 23) & 255) - 127;
        float mu = __int_as_float((__float_as_int(uf) & 0x807FFFFF) | 0x3F800000);
        double log2u = (double)(eu + Ktot) + (double)lg2f(mu);
        g_part[b] = (float)(LN2_D * log2u - (double)tsc_sh);
        __threadfence();
        rank_sh = atomicAdd(&g_done, 1u);
    }
    __syncthreads();

    if (rank_sh == BSZ - 1){
        if (tid < 32){
            double v = (double)__ldcg(&g_part[tid]) + (double)__ldcg(&g_part[tid + 32]);
            #pragma unroll
            for (int m = 16; m > 0; m >>= 1)
                v += __shfl_xor_sync(0xffffffffu, v, m);
            if (tid == 0){
                out[0] = (float)(v * (1.0 / (double)BSZ));
                atomicExch(&g_done, 0u);        // reset for graph replay
            }
        }
    }
}

extern "C" void kernel_launch(void* const* d_in, const int* in_sizes, int n_in,
                              void* d_out, int out_size)
{
    const float* tr  = (const float*)d_in[0];
    const int*   tgt = (const int*)d_in[1];
    float*       out = (float*)d_out;

    dim3 grid(CCH, BSZ);
    crf_chunk_kernel<<<grid, NTH>>>(tr);
    crf_combine_kernel<<<BSZ, NTH>>>(tr, tgt, out);
}

// round 16
// speedup vs baseline: 1.5893x; 1.1833x over previous
#include <cuda_runtime.h>
#include <cstdint>

#define NTAGS 48
#define SEQ 512
#define BSZ 64
#define NTRANS (NTAGS*NTAGS)      // 2304
#define CCH 7                     // chunks per batch
#define LCH 73                    // steps per chunk: 7*73 = 511 (t = 1..511)
#define RST 50                    // fp32 tile row stride (floats), conflict-free
#define STAGES 4
#define NTH 128
#define LOG2E_F 1.4426950408889634f
#define LN2_D   0.6931471805599453
#define START_TAG 46
#define END_TAG 47

__device__ float g_P[BSZ][CCH][NTAGS][NTAGS];   // 4.1 MB chunk matrices (fp32)
__device__ int   g_K[BSZ][CCH];                 // per-chunk power-of-2 exponent
__device__ float g_part[BSZ];
__device__ unsigned int g_done = 0;

__device__ __forceinline__ float ex2f(float x){
    float y; asm("ex2.approx.ftz.f32 %0, %1;" : "=f"(y) : "f"(x)); return y;
}
__device__ __forceinline__ float lg2f(float x){
    float y; asm("lg2.approx.ftz.f32 %0, %1;" : "=f"(y) : "f"(x)); return y;
}
__device__ __forceinline__ uint32_t packbf(float hi, float lo){
    uint32_t r; asm("cvt.rn.bf16x2.f32 %0, %1, %2;" : "=r"(r) : "f"(hi), "f"(lo)); return r;
}
__device__ __forceinline__ void cp8(uint32_t s, const void* g){
    asm volatile("cp.async.ca.shared.global [%0], [%1], 8;" :: "r"(s), "l"(g));
}
__device__ __forceinline__ void mma16816(float d[4],
    uint32_t a0, uint32_t a1, uint32_t a2, uint32_t a3,
    uint32_t b0, uint32_t b1,
    float c0, float c1, float c2, float c3)
{
    asm volatile("mma.sync.aligned.m16n8k16.row.col.f32.bf16.bf16.f32 "
                 "{%0,%1,%2,%3}, {%4,%5,%6,%7}, {%8,%9}, {%10,%11,%12,%13};"
                 : "=f"(d[0]), "=f"(d[1]), "=f"(d[2]), "=f"(d[3])
                 : "r"(a0), "r"(a1), "r"(a2), "r"(a3), "r"(b0), "r"(b1),
                   "f"(c0), "f"(c1), "f"(c2), "f"(c3));
}

// ---------------------------------------------------------------------------
// Kernel 1: P_c = prod exp(tr_t) via bf16 mma chain; 4-stage cp.async pipe.
// ---------------------------------------------------------------------------
__global__ __launch_bounds__(NTH)
void crf_chunk_kernel(const float* __restrict__ tr)
{
    __shared__ __align__(16) float    tile[STAGES][NTAGS*RST]; // 38400 B
    __shared__ __align__(16) uint32_t ET[2][NTAGS*25];         // 9600 B
    __shared__ int k_sh[3];

    const int c = blockIdx.x, b = blockIdx.y;
    const float* trb = tr + (size_t)b * SEQ * NTRANS;
    const int tbeg = 1 + LCH * c;
    const int tend = tbeg + LCH - 1;

    const int tid  = threadIdx.x;
    const int w    = tid >> 5, lane = tid & 31;
    const int g    = lane >> 2, tq = lane & 3;

    uint32_t smo[9]; int gmo[9];
    #pragma unroll
    for (int k = 0; k < 9; ++k){
        int ch = tid + NTH * k;
        int row = ch / 24, off = ch % 24;
        smo[k] = (uint32_t)(row * (RST*4) + off * 8);
        gmo[k] = row * NTAGS + off * 2;
    }
    const uint32_t sb0 = (uint32_t)__cvta_generic_to_shared(&tile[0][0]);

    int eread[9], ewrite[9];
    #pragma unroll
    for (int m = 0; m < 9; ++m){
        int p = tid + NTH * m;
        int j = p % NTAGS, ih = p / NTAGS;
        eread[m]  = (2*ih) * RST + j;
        ewrite[m] = j * 25 + ih;
    }

    auto prefetch = [&](int t){
        uint32_t sb = sb0 + (uint32_t)(t & (STAGES-1)) * (NTAGS*RST*4);
        const float* gb = trb + (size_t)t * NTRANS;
        #pragma unroll
        for (int k = 0; k < 9; ++k) cp8(sb + smo[k], gb + gmo[k]);
    };

    prefetch(tbeg    ); asm volatile("cp.async.commit_group;");
    prefetch(tbeg + 1); asm volatile("cp.async.commit_group;");
    prefetch(tbeg + 2); asm volatile("cp.async.commit_group;");
    prefetch(tbeg + 3); asm volatile("cp.async.commit_group;");
    asm volatile("cp.async.wait_group 3;");   // tile tbeg resident
    __syncthreads();

    // E(tbeg) -> ET[0]
    {
        const float* tl = &tile[tbeg & (STAGES-1)][0];
        #pragma unroll
        for (int m = 0; m < 9; ++m){
            float lo = ex2f(tl[eread[m]      ] * LOG2E_F);
            float hi = ex2f(tl[eread[m] + RST] * LOG2E_F);
            ET[0][ewrite[m]] = packbf(hi, lo);
        }
    }
    __syncthreads();

    // P slice = identity rows [16w, 16w+16)
    float P[6][4];
    const int R0 = 16 * w + g;
    #pragma unroll
    for (int nt = 0; nt < 6; ++nt){
        int C0 = nt * 8 + tq * 2;
        P[nt][0] = (R0     == C0    ) ? 1.f : 0.f;
        P[nt][1] = (R0     == C0 + 1) ? 1.f : 0.f;
        P[nt][2] = (R0 + 8 == C0    ) ? 1.f : 0.f;
        P[nt][3] = (R0 + 8 == C0 + 1) ? 1.f : 0.f;
    }
    int Kw = 0;

    int lp = 0;
    for (int t = tbeg; t <= tend; ++t, lp ^= 1){
        if (t + 4 <= tend) prefetch(t + 4);          // stage t%4 free (consumed t-1)
        asm volatile("cp.async.commit_group;");      // uniform group count
        asm volatile("cp.async.wait_group 3;");      // tiles <= t+1 resident

        if (w < 3){
            // exact pow2 rescale every 4 steps (growth <= 2^44/period: safe)
            if (((t - tbeg) & 3) == 0){
                float diag = __shfl_sync(0xffffffffu, P[2*w][0], 0);
                int   eb   = (__float_as_int(diag) >> 23) & 255;
                float s    = __int_as_float((254 - eb) << 23);
                Kw += eb - 127;
                #pragma unroll
                for (int nt = 0; nt < 6; ++nt){
                    P[nt][0] *= s; P[nt][1] *= s; P[nt][2] *= s; P[nt][3] *= s;
                }
            }
            // D fragments -> A fragments (in registers)
            uint32_t A[3][4];
            #pragma unroll
            for (int kt = 0; kt < 3; ++kt){
                A[kt][0] = packbf(P[2*kt  ][1], P[2*kt  ][0]);
                A[kt][1] = packbf(P[2*kt  ][3], P[2*kt  ][2]);
                A[kt][2] = packbf(P[2*kt+1][1], P[2*kt+1][0]);
                A[kt][3] = packbf(P[2*kt+1][3], P[2*kt+1][2]);
            }
            // P <- P * E
            const uint32_t* Eb = &ET[lp][0];
            #pragma unroll
            for (int nt = 0; nt < 6; ++nt){
                int base = (nt*8 + g) * 25 + tq;
                float d[4] = {0.f, 0.f, 0.f, 0.f};
                #pragma unroll
                for (int kt = 0; kt < 3; ++kt){
                    uint32_t b0 = Eb[base + kt*8];
                    uint32_t b1 = Eb[base + kt*8 + 4];
                    mma16816(d, A[kt][0], A[kt][1], A[kt][2], A[kt][3],
                             b0, b1, d[0], d[1], d[2], d[3]);
                }
                P[nt][0] = d[0]; P[nt][1] = d[1]; P[nt][2] = d[2]; P[nt][3] = d[3];
            }
        }
        // E(t+1) -> ET[lp^1]
        if (t < tend){
            const float* tl = &tile[(t+1) & (STAGES-1)][0];
            uint32_t* Ew = &ET[lp ^ 1][0];
            #pragma unroll
            for (int m = 0; m < 9; ++m){
                float lo = ex2f(tl[eread[m]      ] * LOG2E_F);
                float hi = ex2f(tl[eread[m] + RST] * LOG2E_F);
                Ew[ewrite[m]] = packbf(hi, lo);
            }
        }
        __syncthreads();
    }

    if (w < 3 && lane == 0) k_sh[w] = Kw;
    __syncthreads();
    if (w < 3){
        int kmax = max(k_sh[0], max(k_sh[1], k_sh[2]));
        int d = Kw - kmax;
        float s = (d <= -126) ? 0.f : __int_as_float((127 + d) << 23);
        float* gp = &g_P[b][c][0][0];
        #pragma unroll
        for (int nt = 0; nt < 6; ++nt){
            int C0 = nt * 8 + tq * 2;
            gp[(R0    )*NTAGS + C0    ] = P[nt][0] * s;
            gp[(R0    )*NTAGS + C0 + 1] = P[nt][1] * s;
            gp[(R0 + 8)*NTAGS + C0    ] = P[nt][2] * s;
            gp[(R0 + 8)*NTAGS + C0 + 1] = P[nt][3] * s;
        }
        if (tid == 0) g_K[b][c] = kmax;
    }
}

// ---------------------------------------------------------------------------
// Kernel 2: pipelined combine — cp.async chunk matrices through 3 smem bufs,
// one __syncthreads per chunk, stale-by-one pow2 normalization.
// ---------------------------------------------------------------------------
__global__ __launch_bounds__(NTH)
void crf_combine_kernel(const float* __restrict__ tr,
                        const int*   __restrict__ tgt,
                        float* __restrict__ out)
{
    __shared__ __align__(16) float Pb[3][NTRANS];   // 27648 B
    __shared__ float ub[2][NTAGS];
    __shared__ float red[4];
    __shared__ float tsc_sh;
    __shared__ unsigned int rank_sh;
    __shared__ unsigned char tgs[SEQ];

    const int b = blockIdx.x, tid = threadIdx.x;
    const float* trb = tr + (size_t)b * SEQ * NTRANS;
    const uint32_t pbase = (uint32_t)__cvta_generic_to_shared(&Pb[0][0]);

    auto pf = [&](int c){
        uint32_t sb = pbase + (uint32_t)(c % 3) * (NTRANS*4);
        const float* gp = &g_P[b][c][0][0];
        #pragma unroll
        for (int k = 0; k < 9; ++k){
            int ch = tid + NTH * k;
            cp8(sb + (uint32_t)ch * 8, gp + ch * 2);
        }
    };
    pf(0); asm volatile("cp.async.commit_group;");
    pf(1); asm volatile("cp.async.commit_group;");

    int Kg = 0;                                   // tid 0: sum of chunk exponents
    if (tid == 0){
        #pragma unroll
        for (int c = 0; c < CCH; ++c) Kg += g_K[b][c];
    }

    // targets + target_score (prologue, overlapped with chunk0 load)
    #pragma unroll
    for (int k = 0; k < 4; ++k){
        int i = tid + NTH * k;
        int v = tgt[(size_t)b * SEQ + i];
        tgs[i] = (unsigned char)(((unsigned)v < NTAGS) ? v : 0);
    }
    __syncthreads();
    {
        float acc = 0.f;
        #pragma unroll
        for (int k = 0; k < 4; ++k){
            int t = tid + NTH * k;
            int pr = (t == 0) ? START_TAG : (int)tgs[t-1];
            acc += __ldg(trb + (size_t)t * NTRANS + pr * NTAGS + (int)tgs[t]);
        }
        #pragma unroll
        for (int m = 16; m > 0; m >>= 1) acc += __shfl_xor_sync(0xffffffffu, acc, m);
        if ((tid & 31) == 0) red[tid >> 5] = acc;
    }
    // u0 = exp(tr_0[START,:]) -> ub[1] (chunk 0 reads ub[1], writes ub[0])
    if (tid < NTAGS) ub[1][tid] = ex2f(__ldg(trb + START_TAG * NTAGS + tid) * LOG2E_F);
    __syncthreads();
    if (tid == 0) tsc_sh = (red[0] + red[1]) + (red[2] + red[3]);

    int Ktot = 0;
    for (int c = 0; c < CCH; ++c){
        asm volatile("cp.async.wait_group 1;");   // chunk c resident
        __syncthreads();                          // + prev ub writes visible
        if (c + 2 < CCH) pf(c + 2);               // buffer (c+2)%3 free
        asm volatile("cp.async.commit_group;");

        const float* Pc = &Pb[c % 3][0];
        const float* up = &ub[(c + 1) & 1][0];
        // stale-by-one normalization: uniform k from input u's column 0
        float u0v = up[0];
        int   k   = ((__float_as_int(u0v) >> 23) & 255) - 127;
        Ktot += k;
        if (tid < NTAGS){
            float s = 0.f;
            #pragma unroll 8
            for (int i = 0; i < NTAGS; ++i)
                s = fmaf(up[i], Pc[i * NTAGS + tid], s);
            ub[c & 1][tid] = s * __int_as_float((127 - k) << 23);
        }
    }
    __syncthreads();

    if (tid == 0){
        float uf = ub[(CCH - 1) & 1][END_TAG];
        int   eu = ((__float_as_int(uf) >> 23) & 255) - 127;
        float mu = __int_as_float((__float_as_int(uf) & 0x807FFFFF) | 0x3F800000);
        double log2u = (double)(eu + Ktot + Kg) + (double)lg2f(mu);
        g_part[b] = (float)(LN2_D * log2u - (double)tsc_sh);
        __threadfence();
        rank_sh = atomicAdd(&g_done, 1u);
    }
    __syncthreads();

    if (rank_sh == BSZ - 1){
        if (tid < 32){
            double v = (double)__ldcg(&g_part[tid]) + (double)__ldcg(&g_part[tid + 32]);
            #pragma unroll
            for (int m = 16; m > 0; m >>= 1)
                v += __shfl_xor_sync(0xffffffffu, v, m);
            if (tid == 0){
                out[0] = (float)(v * (1.0 / (double)BSZ));
                atomicExch(&g_done, 0u);          // reset for graph replay
            }
        }
    }
}

extern "C" void kernel_launch(void* const* d_in, const int* in_sizes, int n_in,
                              void* d_out, int out_size)
{
    const float* tr  = (const float*)d_in[0];
    const int*   tgt = (const int*)d_in[1];
    float*       out = (float*)d_out;

    dim3 grid(CCH, BSZ);
    crf_chunk_kernel<<<grid, NTH>>>(tr);
    crf_combine_kernel<<<BSZ, NTH>>>(tr, tgt, out);
}